// round 13
// baseline (speedup 1.0000x reference)
#include <cuda_runtime.h>
#include <cuda_fp16.h>
#include <cstdint>

// Problem constants: B=16, C=128, N=M=2048
#define B_  16
#define C_  128
#define N_  2048
#define K2F  14.4269504089f    // 10 * log2(e)
#define LN2F 0.69314718055995f

#define NTILE   256            // n rows per CTA
#define MCHUNK  32
#define NCHUNKS 64
#define THREADS 512            // 16 warps: pair (2k,2k+1) -> rows k*32, col halves
#define NCTAS   128            // grid 8 x 16

// SMEM u32 layout. B double-buffers (fragment-major) alias the A-stage.
#define APAD   264
#define ASTAGE (64 * APAD)     // 16896 u32; B buffers (2x2048) + combine live here
#define BBUF   2048            // 8 ks x [2 b01][2 half][64] u32
#define POSU   ASTAGE          // red2/posv: 512 floats
#define FLGU   (POSU + 512)
#define SMEMU  (FLGU + 4)

__device__ float g_partial[NCTAS];
__device__ unsigned int g_count;

__device__ __forceinline__ float ex2f(float x) {
    float y;
    asm("ex2.approx.ftz.f32 %0, %1;" : "=f"(y) : "f"(x));
    return y;
}
__device__ __forceinline__ float lg2f(float x) {
    float y;
    asm("lg2.approx.ftz.f32 %0, %1;" : "=f"(y) : "f"(x));
    return y;
}
__device__ __forceinline__ void mma_f16(float* c, const uint32_t* a,
                                        uint32_t b0, uint32_t b1) {
    asm volatile("mma.sync.aligned.m16n8k16.row.col.f32.f16.f16.f32 "
                 "{%0,%1,%2,%3}, {%4,%5,%6,%7}, {%8,%9}, {%0,%1,%2,%3};"
                 : "+f"(c[0]), "+f"(c[1]), "+f"(c[2]), "+f"(c[3])
                 : "r"(a[0]), "r"(a[1]), "r"(a[2]), "r"(a[3]), "r"(b0), "r"(b1));
}

extern __shared__ __align__(16) uint32_t smu[];

__global__ void __launch_bounds__(THREADS, 1)
patchnce_main(const float* __restrict__ q,
              const float* __restrict__ p,
              const float* __restrict__ neg,
              float* __restrict__ out) {
    const int tid  = threadIdx.x;
    const int w    = tid >> 5;
    const int wp   = w >> 1;            // row group: rows wp*32 .. wp*32+31
    const int ch2  = w & 1;             // column half of the 32-col chunk
    const int lane = tid & 31;
    const int g    = lane >> 2;
    const int t4   = lane & 3;
    const int b    = blockIdx.y;
    const int n0   = blockIdx.x * NTILE;

    float* red2 = (float*)&smu[POSU];   // 512; folds to posv[256]
    int*   flag = (int*)&smu[FLGU];

    // ------ Phase 1: stage Q tile as f16x2 kpairs + positive dot -----------
    {
        const int row = tid & 255;
        const int kh  = tid >> 8;
        const float* qb = q + (size_t)b * C_ * N_ + n0 + row;
        const float* pb = p + (size_t)b * C_ * N_ + n0 + row;
        float pd = 0.f;
#pragma unroll 8
        for (int kp = kh * 32; kp < kh * 32 + 32; kp++) {
            float q0 = qb[(size_t)(2 * kp)     * N_];
            float q1 = qb[(size_t)(2 * kp + 1) * N_];
            float p0 = pb[(size_t)(2 * kp)     * N_];
            float p1 = pb[(size_t)(2 * kp + 1) * N_];
            pd = fmaf(q0, p0, fmaf(q1, p1, pd));
            __half2 h = __floats2half2_rn(q0, q1);
            smu[kp * APAD + row] = *(uint32_t*)&h;
        }
        red2[tid] = pd;
    }
    __syncthreads();
    if (tid < 256) red2[tid] += red2[tid + 256];    // posv = red2[0..255]

    // ------ Phase 2: A fragments (2 m16 blocks x 8 ks) -> 64 registers -----
    uint32_t afr[64];
#pragma unroll
    for (int mblk = 0; mblk < 2; mblk++) {
        const int rb = wp * 32 + mblk * 16 + g;
#pragma unroll
        for (int ks = 0; ks < 8; ks++) {
            uint32_t* a = afr + mblk * 32 + ks * 4;
            a[0] = smu[(ks * 8 + t4)     * APAD + rb];
            a[1] = smu[(ks * 8 + t4)     * APAD + rb + 8];
            a[2] = smu[(ks * 8 + t4 + 4) * APAD + rb];
            a[3] = smu[(ks * 8 + t4 + 4) * APAD + rb + 8];
        }
    }
    __syncthreads();   // A-stage region becomes B buffers

    // ------ Phase 3: chunk loop -------------------------------------------
    const float* nb = neg + (size_t)b * C_ * N_;
    const int kp  = tid >> 3;          // producer kpair 0..63
    const int mq  = tid & 7;           // producer m-quad

    // producer scatter base (fragment-major): [ks][b01][half][lane*2+gIdx]
    const int pks  = kp >> 3;
    const int pb01 = (kp & 7) >> 2;
    const int pt4  = kp & 3;
    const int pgrp = mq >> 1;                       // global n8 group (fixed)
    const int g0   = (mq & 1) * 4;                  // first g of the 4 cols
    const uint32_t pbase = (uint32_t)(pks * 256 + pb01 * 128 + (pgrp >> 1) * 64
                                      + pt4 * 2 + (pgrp & 1));

    float4 pr0, pr1;
    auto loadB = [&](int ch) {
        const float* s = nb + ch * MCHUNK + mq * 4;
        pr0 = *(const float4*)(s + (size_t)(2 * kp)     * N_);
        pr1 = *(const float4*)(s + (size_t)(2 * kp + 1) * N_);
    };
    auto storeB = [&](int buf) {
        uint32_t* bb = smu + buf * BBUF;
        __half2 h0 = __floats2half2_rn(pr0.x, pr1.x);
        __half2 h1 = __floats2half2_rn(pr0.y, pr1.y);
        __half2 h2 = __floats2half2_rn(pr0.z, pr1.z);
        __half2 h3 = __floats2half2_rn(pr0.w, pr1.w);
        bb[pbase + (g0 + 0) * 8] = *(uint32_t*)&h0;
        bb[pbase + (g0 + 1) * 8] = *(uint32_t*)&h1;
        bb[pbase + (g0 + 2) * 8] = *(uint32_t*)&h2;
        bb[pbase + (g0 + 3) * 8] = *(uint32_t*)&h3;
    };

    float rmax2[4], rsum[4];
#pragma unroll
    for (int s = 0; s < 4; s++) { rmax2[s] = -1e30f; rsum[s] = 0.f; }

    // Prologue
    loadB(0); storeB(0); loadB(1);
    __syncthreads();

#pragma unroll 1
    for (int ch = 0; ch < NCHUNKS; ch++) {
        const uint32_t* bb = smu + (ch & 1) * BBUF + ch2 * 64 + lane * 2;
        float acc[2][2][4];            // [mblk][glocal][c]
#pragma unroll
        for (int i = 0; i < 2; i++)
#pragma unroll
            for (int j = 0; j < 2; j++)
#pragma unroll
                for (int k = 0; k < 4; k++) acc[i][j][k] = 0.f;

#pragma unroll
        for (int ks = 0; ks < 8; ks++) {
            uint2 b0 = *(const uint2*)&bb[ks * 256];
            uint2 b1 = *(const uint2*)&bb[ks * 256 + 128];
            mma_f16(acc[0][0], afr + ks * 4,      b0.x, b1.x);
            mma_f16(acc[0][1], afr + ks * 4,      b0.y, b1.y);
            mma_f16(acc[1][0], afr + 32 + ks * 4, b0.x, b1.x);
            mma_f16(acc[1][1], afr + 32 + ks * 4, b0.y, b1.y);
        }

        // softmax: 4 slots (mblk, half), 4 values each
#pragma unroll
        for (int mblk = 0; mblk < 2; mblk++) {
#pragma unroll
            for (int h = 0; h < 2; h++) {
                const int s = mblk * 2 + h;
                float v0 = acc[mblk][0][h*2], v1 = acc[mblk][0][h*2+1];
                float v2 = acc[mblk][1][h*2], v3 = acc[mblk][1][h*2+1];
                float vm = fmaxf(fmaxf(v0, v1), fmaxf(v2, v3));
                float nm = fmaxf(rmax2[s], vm * K2F);
                rsum[s] *= ex2f(rmax2[s] - nm);
                rmax2[s] = nm;
                __half2 e01 = h2exp2(__floats2half2_rn(fmaf(v0, K2F, -nm),
                                                       fmaf(v1, K2F, -nm)));
                __half2 e23 = h2exp2(__floats2half2_rn(fmaf(v2, K2F, -nm),
                                                       fmaf(v3, K2F, -nm)));
                float2 f = __half22float2(__hadd2(e01, e23));
                rsum[s] += f.x + f.y;
            }
        }

        // stage next-next chunk (buffer (ch+1)&1 was last read in iter ch-1,
        // separated by this iteration's entry barrier)
        if (ch + 1 < NCHUNKS) storeB((ch + 1) & 1);
        if (ch + 2 < NCHUNKS) loadB(ch + 2);
        __syncthreads();
    }

    // ------ Combine: t4 lanes, then warp pairs via smem --------------------
#pragma unroll
    for (int s = 0; s < 4; s++) {
#pragma unroll
        for (int d = 1; d <= 2; d <<= 1) {
            float om = __shfl_xor_sync(0xFFFFFFFFu, rmax2[s], d);
            float os = __shfl_xor_sync(0xFFFFFFFFu, rsum[s], d);
            float nm = fmaxf(rmax2[s], om);
            rsum[s] = rsum[s] * ex2f(rmax2[s] - nm) + os * ex2f(om - nm);
            rmax2[s] = nm;
        }
    }
    float* cmax = (float*)smu;          // [256][2]
    float* csum = (float*)&smu[512];    // [256][2]
    if (t4 == 0) {
#pragma unroll
        for (int s = 0; s < 4; s++) {
            const int row = wp * 32 + (s >> 1) * 16 + (s & 1) * 8 + g;
            cmax[row * 2 + ch2] = rmax2[s];
            csum[row * 2 + ch2] = rsum[s];
        }
    }
    __syncthreads();

    float loss = 0.f;
    if (tid < 256) {
        float m0 = cmax[tid * 2],     s0 = csum[tid * 2];
        float m1 = cmax[tid * 2 + 1], s1 = csum[tid * 2 + 1];
        float nm = fmaxf(m0, m1);
        float S  = s0 * ex2f(m0 - nm) + s1 * ex2f(m1 - nm);
        float lp2 = red2[tid] * K2F;
        float M2 = fmaxf(nm, lp2);
        float S2 = S * ex2f(nm - M2) + ex2f(lp2 - M2);
        loss = (M2 + lg2f(S2) - lp2) * LN2F;
    }

    // ------ Deterministic per-CTA reduction --------------------------------
    __syncthreads();
    float* tmp = (float*)&smu[1024];
    tmp[tid] = loss;
    __syncthreads();
    for (int o = 256; o > 0; o >>= 1) {
        if (tid < o) tmp[tid] += tmp[tid + o];
        __syncthreads();
    }

    // ------ Cross-CTA fold: last CTA finishes ------------------------------
    const int cta = blockIdx.y * 8 + blockIdx.x;
    if (tid == 0) {
        g_partial[cta] = tmp[0];
        __threadfence();
        unsigned v = atomicAdd(&g_count, 1u);
        *flag = (v == NCTAS - 1) ? 1 : 0;
    }
    __syncthreads();
    if (*flag) {
        __threadfence();
        tmp[tid] = (tid < NCTAS) ? g_partial[tid] : 0.f;
        __syncthreads();
        for (int o = 64; o > 0; o >>= 1) {
            if (tid < o) tmp[tid] += tmp[tid + o];
            __syncthreads();
        }
        if (tid == 0) {
            out[0] = tmp[0] / (float)(B_ * N_);
            g_count = 0;
        }
    }
}

// ---------------------------------------------------------------------------
extern "C" void kernel_launch(void* const* d_in, const int* in_sizes, int n_in,
                              void* d_out, int out_size) {
    const float* q   = (const float*)d_in[0];
    const float* pos = (const float*)d_in[1];
    const float* neg = (const float*)d_in[2];
    float* out = (float*)d_out;

    cudaFuncSetAttribute(patchnce_main,
                         cudaFuncAttributeMaxDynamicSharedMemorySize,
                         SMEMU * sizeof(uint32_t));
    patchnce_main<<<dim3(8, 16), THREADS, SMEMU * sizeof(uint32_t)>>>(q, pos, neg, out);
}

// round 14
// speedup vs baseline: 1.0602x; 1.0602x over previous
#include <cuda_runtime.h>
#include <cuda_fp16.h>
#include <cstdint>

// Problem constants: B=16, C=128, N=M=2048
#define B_  16
#define C_  128
#define N_  2048
#define K2F  14.4269504089f    // 10 * log2(e)
#define LN2F 0.69314718055995f

#define NTILE   256            // n rows per CTA; 32 per warp (8 warps)
#define MCHUNK  64             // columns staged per barrier (2 x 32-col halves)
#define NCHUNKS 32
#define THREADS 256
#define NCTAS   128            // grid 8 x 16

// SMEM u32 layout. B double-buffers (fragment-major) alias the A-stage.
#define APAD   264
#define ASTAGE (64 * APAD)     // 16896 u32
#define BBUF   4096            // 8 ks x [2 b01][2 half][128] u32
#define POSU   ASTAGE          // posv[256] floats
#define FLGU   (POSU + 256)
#define SMEMU  (FLGU + 4)

__device__ float g_partial[NCTAS];
__device__ unsigned int g_count;

__device__ __forceinline__ float ex2f(float x) {
    float y;
    asm("ex2.approx.ftz.f32 %0, %1;" : "=f"(y) : "f"(x));
    return y;
}
__device__ __forceinline__ float lg2f(float x) {
    float y;
    asm("lg2.approx.ftz.f32 %0, %1;" : "=f"(y) : "f"(x));
    return y;
}
__device__ __forceinline__ void mma_f16(float* c, const uint32_t* a,
                                        uint32_t b0, uint32_t b1) {
    asm volatile("mma.sync.aligned.m16n8k16.row.col.f32.f16.f16.f32 "
                 "{%0,%1,%2,%3}, {%4,%5,%6,%7}, {%8,%9}, {%0,%1,%2,%3};"
                 : "+f"(c[0]), "+f"(c[1]), "+f"(c[2]), "+f"(c[3])
                 : "r"(a[0]), "r"(a[1]), "r"(a[2]), "r"(a[3]), "r"(b0), "r"(b1));
}

extern __shared__ __align__(16) uint32_t smu[];

__global__ void __launch_bounds__(THREADS, 1)
patchnce_main(const float* __restrict__ q,
              const float* __restrict__ p,
              const float* __restrict__ neg,
              float* __restrict__ out) {
    const int tid  = threadIdx.x;
    const int w    = tid >> 5;          // 8 warps; rows w*32 .. w*32+31
    const int lane = tid & 31;
    const int g    = lane >> 2;
    const int t4   = lane & 3;
    const int b    = blockIdx.y;
    const int n0   = blockIdx.x * NTILE;

    float* posv = (float*)&smu[POSU];
    int*   flag = (int*)&smu[FLGU];

    // ------ Phase 1: stage Q tile as f16x2 kpairs + positive dot -----------
    {
        const float* qb = q + (size_t)b * C_ * N_ + n0 + tid;
        const float* pb = p + (size_t)b * C_ * N_ + n0 + tid;
        float pd = 0.f;
#pragma unroll 8
        for (int kp = 0; kp < 64; kp++) {
            float q0 = qb[(size_t)(2 * kp)     * N_];
            float q1 = qb[(size_t)(2 * kp + 1) * N_];
            float p0 = pb[(size_t)(2 * kp)     * N_];
            float p1 = pb[(size_t)(2 * kp + 1) * N_];
            pd = fmaf(q0, p0, fmaf(q1, p1, pd));
            __half2 h = __floats2half2_rn(q0, q1);
            smu[kp * APAD + tid] = *(uint32_t*)&h;
        }
        posv[tid] = pd;
    }
    __syncthreads();

    // ------ Phase 2: A fragments (2 m16 blocks x 8 ks) -> 64 registers -----
    uint32_t afr[64];
#pragma unroll
    for (int mblk = 0; mblk < 2; mblk++) {
        const int rb = w * 32 + mblk * 16 + g;
#pragma unroll
        for (int ks = 0; ks < 8; ks++) {
            uint32_t* a = afr + mblk * 32 + ks * 4;
            a[0] = smu[(ks * 8 + t4)     * APAD + rb];
            a[1] = smu[(ks * 8 + t4)     * APAD + rb + 8];
            a[2] = smu[(ks * 8 + t4 + 4) * APAD + rb];
            a[3] = smu[(ks * 8 + t4 + 4) * APAD + rb + 8];
        }
    }
    __syncthreads();   // A-stage region becomes B buffers

    // ------ Phase 3: chunk loop (64 cols, fragment-major B) ----------------
    const float* nb = neg + (size_t)b * C_ * N_;
    // Producer coords: thread stages kpair kp (rows 2kp,2kp+1), 16 cols.
    const int kp  = tid >> 2;          // 0..63
    const int nq  = tid & 3;           // col quarter: n = nq*16 + 0..15
    const int pks = kp >> 3;
    const int pb01 = (kp & 7) >> 2;
    const int pt4 = kp & 3;
    const uint32_t pbase = (uint32_t)(pks * 512 + pb01 * 256 + pt4 * 4);
    const int grpA = nq * 2, grpB = nq * 2 + 1;
    const uint32_t offA = (uint32_t)((grpA >> 2) * 128 + (grpA & 3));
    const uint32_t offB = (uint32_t)((grpB >> 2) * 128 + (grpB & 3));

    float4 pr0[4], pr1[4];
    auto loadB = [&](int ch) {
        const float* s = nb + ch * MCHUNK + nq * 16;
#pragma unroll
        for (int i = 0; i < 4; i++) {
            pr0[i] = *(const float4*)(s + (size_t)(2 * kp)     * N_ + i * 4);
            pr1[i] = *(const float4*)(s + (size_t)(2 * kp + 1) * N_ + i * 4);
        }
    };
    auto storeB = [&](int buf) {
        uint32_t* bb = smu + buf * BBUF + pbase;
#pragma unroll
        for (int i = 0; i < 4; i++) {
            const float* a0 = (const float*)&pr0[i];
            const float* a1 = (const float*)&pr1[i];
#pragma unroll
            for (int c = 0; c < 4; c++) {
                const int jj = i * 4 + c;
                __half2 h = __floats2half2_rn(a0[c], a1[c]);
                const uint32_t off = (jj < 8 ? offA : offB) + (uint32_t)((jj & 7) * 16);
                bb[off] = *(uint32_t*)&h;
            }
        }
    };

    float rmax2[4], rsum[4];
#pragma unroll
    for (int s = 0; s < 4; s++) { rmax2[s] = -1e30f; rsum[s] = 0.f; }

    float acc0[4][2][4], acc1[4][2][4];

    auto softmax_slot = [&](float (&acc)[4][2][4], int s) {
        const int mblk = s >> 1, hr = s & 1;
        float v0 = acc[0][mblk][hr*2], v1 = acc[0][mblk][hr*2+1];
        float v2 = acc[1][mblk][hr*2], v3 = acc[1][mblk][hr*2+1];
        float v4 = acc[2][mblk][hr*2], v5 = acc[2][mblk][hr*2+1];
        float v6 = acc[3][mblk][hr*2], v7 = acc[3][mblk][hr*2+1];
        float vm = fmaxf(fmaxf(fmaxf(v0, v1), fmaxf(v2, v3)),
                         fmaxf(fmaxf(v4, v5), fmaxf(v6, v7)));
        float nm = fmaxf(rmax2[s], vm * K2F);
        rsum[s] *= ex2f(rmax2[s] - nm);
        rmax2[s] = nm;
        __half2 e01 = h2exp2(__floats2half2_rn(fmaf(v0, K2F, -nm), fmaf(v1, K2F, -nm)));
        __half2 e23 = h2exp2(__floats2half2_rn(fmaf(v2, K2F, -nm), fmaf(v3, K2F, -nm)));
        __half2 e45 = h2exp2(__floats2half2_rn(fmaf(v4, K2F, -nm), fmaf(v5, K2F, -nm)));
        __half2 e67 = h2exp2(__floats2half2_rn(fmaf(v6, K2F, -nm), fmaf(v7, K2F, -nm)));
        __half2 st = __hadd2(__hadd2(e01, e23), __hadd2(e45, e67));
        float2 f = __half22float2(st);
        rsum[s] += f.x + f.y;
    };
    auto softmax_full = [&](float (&acc)[4][2][4]) {
#pragma unroll
        for (int s = 0; s < 4; s++) softmax_slot(acc, s);
    };

    // MMA over one 32-col half: 2 LDS.128 per ks, softmax of other acc at odd ks.
    auto mma_half = [&](int buf, int h, float (&aN)[4][2][4],
                        float (&aO)[4][2][4], bool doSoft) {
        const uint32_t* bb = smu + buf * BBUF + h * 128 + lane * 4;
#pragma unroll
        for (int i = 0; i < 4; i++)
#pragma unroll
            for (int m = 0; m < 2; m++)
#pragma unroll
                for (int j = 0; j < 4; j++) aN[i][m][j] = 0.f;

        uint4 c0 = *(const uint4*)&bb[0];
        uint4 c1 = *(const uint4*)&bb[256];
#pragma unroll
        for (int ks = 0; ks < 8; ks++) {
            uint4 n0v = c0, n1v = c1;
            if (ks < 7) {
                n0v = *(const uint4*)&bb[(ks + 1) * 512];
                n1v = *(const uint4*)&bb[(ks + 1) * 512 + 256];
            }
            mma_f16(aN[0][0], afr + ks * 4,      c0.x, c1.x);
            mma_f16(aN[1][0], afr + ks * 4,      c0.y, c1.y);
            mma_f16(aN[2][0], afr + ks * 4,      c0.z, c1.z);
            mma_f16(aN[3][0], afr + ks * 4,      c0.w, c1.w);
            mma_f16(aN[0][1], afr + 32 + ks * 4, c0.x, c1.x);
            mma_f16(aN[1][1], afr + 32 + ks * 4, c0.y, c1.y);
            mma_f16(aN[2][1], afr + 32 + ks * 4, c0.z, c1.z);
            mma_f16(aN[3][1], afr + 32 + ks * 4, c0.w, c1.w);
            if (doSoft && (ks & 1)) softmax_slot(aO, ks >> 1);
            c0 = n0v; c1 = n1v;
        }
    };

    // Prologue: stage chunk0, preload chunk1, MMA chunk0 half0.
    loadB(0); storeB(0); loadB(1);
    __syncthreads();
    mma_half(0, 0, acc0, acc1, false);

#pragma unroll 1
    for (int ch = 0; ch < NCHUNKS; ch++) {
        const int bf = ch & 1;
        mma_half(bf, 1, acc1, acc0, true);        // half1 MMA || softmax half0
        if (ch + 1 < NCHUNKS) storeB((ch + 1) & 1);
        if (ch + 2 < NCHUNKS) loadB(ch + 2);
        __syncthreads();
        if (ch + 1 < NCHUNKS) {
            mma_half((ch + 1) & 1, 0, acc0, acc1, true);  // next half0 || softmax half1
        } else {
            softmax_full(acc1);
        }
    }

    // ------ Combine the 4 lanes (t4) sharing each row ----------------------
#pragma unroll
    for (int s = 0; s < 4; s++) {
#pragma unroll
        for (int d = 1; d <= 2; d <<= 1) {
            float om = __shfl_xor_sync(0xFFFFFFFFu, rmax2[s], d);
            float os = __shfl_xor_sync(0xFFFFFFFFu, rsum[s], d);
            float nm = fmaxf(rmax2[s], om);
            rsum[s] = rsum[s] * ex2f(rmax2[s] - nm) + os * ex2f(om - nm);
            rmax2[s] = nm;
        }
    }

    float loss = 0.f;
    if (t4 == 0) {
#pragma unroll
        for (int s = 0; s < 4; s++) {
            const int r = w * 32 + (s >> 1) * 16 + (s & 1) * 8 + g;
            float lp2 = posv[r] * K2F;
            float M2 = fmaxf(rmax2[s], lp2);
            float S2 = rsum[s] * ex2f(rmax2[s] - M2) + ex2f(lp2 - M2);
            loss += (M2 + lg2f(S2) - lp2) * LN2F;
        }
    }

    // ------ Deterministic per-CTA reduction --------------------------------
    __syncthreads();
    float* tmp = (float*)smu;
    tmp[tid] = loss;
    __syncthreads();
    for (int o = 128; o > 0; o >>= 1) {
        if (tid < o) tmp[tid] += tmp[tid + o];
        __syncthreads();
    }

    // ------ Cross-CTA fold: last CTA finishes ------------------------------
    const int cta = blockIdx.y * 8 + blockIdx.x;
    if (tid == 0) {
        g_partial[cta] = tmp[0];
        __threadfence();
        unsigned v = atomicAdd(&g_count, 1u);
        *flag = (v == NCTAS - 1) ? 1 : 0;
    }
    __syncthreads();
    if (*flag) {
        __threadfence();
        tmp[tid] = (tid < NCTAS) ? g_partial[tid] : 0.f;
        __syncthreads();
        for (int o = 64; o > 0; o >>= 1) {
            if (tid < o) tmp[tid] += tmp[tid + o];
            __syncthreads();
        }
        if (tid == 0) {
            out[0] = tmp[0] / (float)(B_ * N_);
            g_count = 0;
        }
    }
}

// ---------------------------------------------------------------------------
extern "C" void kernel_launch(void* const* d_in, const int* in_sizes, int n_in,
                              void* d_out, int out_size) {
    const float* q   = (const float*)d_in[0];
    const float* pos = (const float*)d_in[1];
    const float* neg = (const float*)d_in[2];
    float* out = (float*)d_out;

    cudaFuncSetAttribute(patchnce_main,
                         cudaFuncAttributeMaxDynamicSharedMemorySize,
                         SMEMU * sizeof(uint32_t));
    patchnce_main<<<dim3(8, 16), THREADS, SMEMU * sizeof(uint32_t)>>>(q, pos, neg, out);
}

// round 16
// speedup vs baseline: 1.2292x; 1.1595x over previous
#include <cuda_runtime.h>
#include <cuda_fp16.h>
#include <cstdint>

// Problem constants: B=16, C=128, N=M=2048
#define B_  16
#define C_  128
#define N_  2048
#define K2F  14.4269504089f    // 10 * log2(e)
#define LN2F 0.69314718055995f

#define NTILE   256
#define MCHUNK  32
#define NCHUNKS 64
#define THREADS 256
#define NCTAS   128            // grid 8 x 16

#define APAD   264
#define ASTAGE (64 * APAD)     // 16896 u32
#define BP     40
#define BBUF   (64 * BP)       // 2560 u32; 4 buffers = 10240 (alias A-stage)
#define POSU   ASTAGE
#define FLGU   (POSU + 256)
#define SMEMU  (FLGU + 4)

__device__ float g_partial[NCTAS];
__device__ unsigned int g_count;

__device__ __forceinline__ float ex2f(float x) {
    float y;
    asm("ex2.approx.ftz.f32 %0, %1;" : "=f"(y) : "f"(x));
    return y;
}
__device__ __forceinline__ float lg2f(float x) {
    float y;
    asm("lg2.approx.ftz.f32 %0, %1;" : "=f"(y) : "f"(x));
    return y;
}
__device__ __forceinline__ void mma_f16(float* c, const uint32_t* a,
                                        uint32_t b0, uint32_t b1) {
    asm volatile("mma.sync.aligned.m16n8k16.row.col.f32.f16.f16.f32 "
                 "{%0,%1,%2,%3}, {%4,%5,%6,%7}, {%8,%9}, {%0,%1,%2,%3};"
                 : "+f"(c[0]), "+f"(c[1]), "+f"(c[2]), "+f"(c[3])
                 : "r"(a[0]), "r"(a[1]), "r"(a[2]), "r"(a[3]), "r"(b0), "r"(b1));
}

extern __shared__ uint32_t smu[];

__global__ void __launch_bounds__(THREADS, 1)
patchnce_main(const float* __restrict__ q,
              const float* __restrict__ p,
              const float* __restrict__ neg,
              float* __restrict__ out) {
    const int tid  = threadIdx.x;
    const int w    = tid >> 5;
    const int lane = tid & 31;
    const int g    = lane >> 2;
    const int t4   = lane & 3;
    const int b    = blockIdx.y;
    const int n0   = blockIdx.x * NTILE;

    float* posv = (float*)&smu[POSU];
    int*   flag = (int*)&smu[FLGU];

    // ------ Phase 1: stage Q tile as f16x2 kpairs + positive dot -----------
    {
        const float* qb = q + (size_t)b * C_ * N_ + n0 + tid;
        const float* pb = p + (size_t)b * C_ * N_ + n0 + tid;
        float pd = 0.f;
#pragma unroll 8
        for (int kp = 0; kp < 64; kp++) {
            float q0 = qb[(size_t)(2 * kp)     * N_];
            float q1 = qb[(size_t)(2 * kp + 1) * N_];
            float p0 = pb[(size_t)(2 * kp)     * N_];
            float p1 = pb[(size_t)(2 * kp + 1) * N_];
            pd = fmaf(q0, p0, fmaf(q1, p1, pd));
            __half2 h = __floats2half2_rn(q0, q1);
            smu[kp * APAD + tid] = *(uint32_t*)&h;
        }
        posv[tid] = pd;
    }
    __syncthreads();

    // ------ Phase 2: A fragments -> 64 registers ---------------------------
    uint32_t afr[64];
#pragma unroll
    for (int mblk = 0; mblk < 2; mblk++) {
        const int rb = w * 32 + mblk * 16 + g;
#pragma unroll
        for (int ks = 0; ks < 8; ks++) {
            uint32_t* a = afr + mblk * 32 + ks * 4;
            a[0] = smu[(ks * 8 + t4)     * APAD + rb];
            a[1] = smu[(ks * 8 + t4)     * APAD + rb + 8];
            a[2] = smu[(ks * 8 + t4 + 4) * APAD + rb];
            a[3] = smu[(ks * 8 + t4 + 4) * APAD + rb + 8];
        }
    }
    __syncthreads();   // A-stage region becomes the 4 B buffers

    // ------ Phase 3: 4-buffer pipeline, barrier every 2 chunks -------------
    const float* nb = neg + (size_t)b * C_ * N_;
    const int kp0 = tid >> 3;
    const int mq  = tid & 7;

    float4 pr[4];
    auto loadB = [&](int ch) {
        const float* s = nb + ch * MCHUNK + mq * 4;
#pragma unroll
        for (int i = 0; i < 2; i++) {
            const int kp = kp0 + i * 32;
            pr[i * 2 + 0] = *(const float4*)(s + (size_t)(2 * kp)     * N_);
            pr[i * 2 + 1] = *(const float4*)(s + (size_t)(2 * kp + 1) * N_);
        }
    };
    auto storeB = [&](int buf) {
        uint32_t* bb = smu + buf * BBUF;
#pragma unroll
        for (int i = 0; i < 2; i++) {
            const int kp = kp0 + i * 32;
            __half2 h0 = __floats2half2_rn(pr[i*2].x, pr[i*2+1].x);
            __half2 h1 = __floats2half2_rn(pr[i*2].y, pr[i*2+1].y);
            __half2 h2 = __floats2half2_rn(pr[i*2].z, pr[i*2+1].z);
            __half2 h3 = __floats2half2_rn(pr[i*2].w, pr[i*2+1].w);
            uint4 v = { *(uint32_t*)&h0, *(uint32_t*)&h1,
                        *(uint32_t*)&h2, *(uint32_t*)&h3 };
            *(uint4*)&smu[buf * BBUF + kp * BP + mq * 4] = v;
            (void)bb;
        }
    };

    float rmax2[4], rsum[4];
#pragma unroll
    for (int s = 0; s < 4; s++) { rmax2[s] = -1e30f; rsum[s] = 0.f; }

    float acc0[4][2][4], acc1[4][2][4];

    auto softmax_slot = [&](float (&acc)[4][2][4], int s) {
        const int mblk = s >> 1, h = s & 1;
        float v0 = acc[0][mblk][h*2], v1 = acc[0][mblk][h*2+1];
        float v2 = acc[1][mblk][h*2], v3 = acc[1][mblk][h*2+1];
        float v4 = acc[2][mblk][h*2], v5 = acc[2][mblk][h*2+1];
        float v6 = acc[3][mblk][h*2], v7 = acc[3][mblk][h*2+1];
        float vm = fmaxf(fmaxf(fmaxf(v0, v1), fmaxf(v2, v3)),
                         fmaxf(fmaxf(v4, v5), fmaxf(v6, v7)));
        float nm = fmaxf(rmax2[s], vm * K2F);
        rsum[s] *= ex2f(rmax2[s] - nm);
        rmax2[s] = nm;
        const float r = nm;
        __half2 e01 = h2exp2(__floats2half2_rn(fmaf(v0, K2F, -r), fmaf(v1, K2F, -r)));
        __half2 e23 = h2exp2(__floats2half2_rn(fmaf(v2, K2F, -r), fmaf(v3, K2F, -r)));
        __half2 e45 = h2exp2(__floats2half2_rn(fmaf(v4, K2F, -r), fmaf(v5, K2F, -r)));
        __half2 e67 = h2exp2(__floats2half2_rn(fmaf(v6, K2F, -r), fmaf(v7, K2F, -r)));
        __half2 st = __hadd2(__hadd2(e01, e23), __hadd2(e45, e67));
        float2 f = __half22float2(st);
        rsum[s] += f.x + f.y;
    };
    auto softmax_full = [&](float (&acc)[4][2][4]) {
#pragma unroll
        for (int s = 0; s < 4; s++) softmax_slot(acc, s);
    };

    auto fused = [&](int buf, float (&aN)[4][2][4], float (&aO)[4][2][4],
                     bool doSoft) {
        const uint32_t* bb = smu + buf * BBUF;
#pragma unroll
        for (int i = 0; i < 4; i++)
#pragma unroll
            for (int m = 0; m < 2; m++)
#pragma unroll
                for (int j = 0; j < 4; j++) aN[i][m][j] = 0.f;

        uint32_t bc[8], bn[8];
#pragma unroll
        for (int grp = 0; grp < 4; grp++) {
            bc[grp]     = bb[t4 * BP + grp * 8 + g];
            bc[4 + grp] = bb[(t4 + 4) * BP + grp * 8 + g];
        }
#pragma unroll
        for (int ks = 0; ks < 8; ks++) {
            if (ks < 7) {
#pragma unroll
                for (int grp = 0; grp < 4; grp++) {
                    bn[grp]     = bb[((ks + 1) * 8 + t4)     * BP + grp * 8 + g];
                    bn[4 + grp] = bb[((ks + 1) * 8 + t4 + 4) * BP + grp * 8 + g];
                }
            }
#pragma unroll
            for (int grp = 0; grp < 4; grp++) {
                mma_f16(aN[grp][0], afr + ks * 4,      bc[grp], bc[4 + grp]);
                mma_f16(aN[grp][1], afr + 32 + ks * 4, bc[grp], bc[4 + grp]);
            }
            if (doSoft && (ks & 1)) softmax_slot(aO, ks >> 1);
#pragma unroll
            for (int i = 0; i < 8; i++) bc[i] = bn[i];
        }
    };

    // Prologue: fill buffers 0,1; pr holds chunk 2; MMA chunk 0.
    loadB(0); storeB(0); loadB(1); storeB(1); loadB(2);
    __syncthreads();
    fused(0, acc0, acc1, false);

    // Pair loop: one barrier per 2 chunks. Invariant at top: MMA(ch) done
    // into acc0; buffers ch,ch+1 full; pr holds ch+2.
#pragma unroll 1
    for (int ch = 0; ch < NCHUNKS; ch += 2) {
        if (ch + 2 < NCHUNKS) {               // buf (ch+2)&3: last read MMA(ch-2),
            storeB((ch + 2) & 3);             // finished before previous barrier
            if (ch + 3 < NCHUNKS) loadB(ch + 3);
        }
        if (ch + 1 < NCHUNKS)                 // MMA(ch+1) + softmax(ch) — no barrier!
            fused((ch + 1) & 3, acc1, acc0, true);
        else
            softmax_full(acc0);
        if (ch + 3 < NCHUNKS) {               // buf (ch+3)&3: last read MMA(ch-1)
            storeB((ch + 3) & 3);
            if (ch + 4 < NCHUNKS) loadB(ch + 4);
        }
        __syncthreads();
        if (ch + 2 < NCHUNKS)
            fused((ch + 2) & 3, acc0, acc1, true);   // MMA(ch+2) + softmax(ch+1)
        else if (ch + 1 < NCHUNKS)
            softmax_full(acc1);
    }

    // ------ Combine the 4 lanes (t4) sharing each row ----------------------
#pragma unroll
    for (int s = 0; s < 4; s++) {
#pragma unroll
        for (int d = 1; d <= 2; d <<= 1) {
            float om = __shfl_xor_sync(0xFFFFFFFFu, rmax2[s], d);
            float os = __shfl_xor_sync(0xFFFFFFFFu, rsum[s], d);
            float nm = fmaxf(rmax2[s], om);
            rsum[s] = rsum[s] * ex2f(rmax2[s] - nm) + os * ex2f(om - nm);
            rmax2[s] = nm;
        }
    }

    float loss = 0.f;
    if (t4 == 0) {
#pragma unroll
        for (int mblk = 0; mblk < 2; mblk++) {
#pragma unroll
            for (int h = 0; h < 2; h++) {
                const int s = mblk * 2 + h;
                const int r = w * 32 + mblk * 16 + h * 8 + g;
                float lp2 = posv[r] * K2F;
                float M2 = fmaxf(rmax2[s], lp2);
                float S2 = rsum[s] * ex2f(rmax2[s] - M2) + ex2f(lp2 - M2);
                loss += (M2 + lg2f(S2) - lp2) * LN2F;
            }
        }
    }

    // ------ Deterministic per-CTA reduction --------------------------------
    __syncthreads();
    float* tmp = (float*)smu;
    tmp[tid] = loss;
    __syncthreads();
    for (int o = 128; o > 0; o >>= 1) {
        if (tid < o) tmp[tid] += tmp[tid + o];
        __syncthreads();
    }

    // ------ Cross-CTA fold: last CTA finishes ------------------------------
    const int cta = blockIdx.y * 8 + blockIdx.x;
    if (tid == 0) {
        g_partial[cta] = tmp[0];
        __threadfence();
        unsigned v = atomicAdd(&g_count, 1u);
        *flag = (v == NCTAS - 1) ? 1 : 0;
    }
    __syncthreads();
    if (*flag) {
        __threadfence();
        tmp[tid] = (tid < NCTAS) ? g_partial[tid] : 0.f;
        __syncthreads();
        for (int o = 64; o > 0; o >>= 1) {
            if (tid < o) tmp[tid] += tmp[tid + o];
            __syncthreads();
        }
        if (tid == 0) {
            out[0] = tmp[0] / (float)(B_ * N_);
            g_count = 0;
        }
    }
}

// ---------------------------------------------------------------------------
extern "C" void kernel_launch(void* const* d_in, const int* in_sizes, int n_in,
                              void* d_out, int out_size) {
    const float* q   = (const float*)d_in[0];
    const float* pos = (const float*)d_in[1];
    const float* neg = (const float*)d_in[2];
    float* out = (float*)d_out;

    cudaFuncSetAttribute(patchnce_main,
                         cudaFuncAttributeMaxDynamicSharedMemorySize,
                         SMEMU * sizeof(uint32_t));
    patchnce_main<<<dim3(8, 16), THREADS, SMEMU * sizeof(uint32_t)>>>(q, pos, neg, out);
}